// round 11
// baseline (speedup 1.0000x reference)
#include <cuda_runtime.h>
#include <cuda.h>
#include <stdint.h>

// StationSelectionAggregator:
//   schedule: [B, WIN, N_ST]  one-hot float32
//   csi:      [B, N_ST, N_SUB, WIN] float32
//   out:      [B, WIN, N_SUB] float32
//   out[b,w,s] = csi[b, t(b,w), s, w]  (exact selection; schedule one-hot).
//
// R11: R10's TMA dense stage (first kernel to beat the LDG plateau,
// 6.89 TB/s) + double-buffered pipeline: each CTA owns one (w-tile, batch)
// and loops over the 8 s-tiles, prefetching tile sT+1 via TMA while
// consuming tile sT. Removes the per-tile TMA-wait bubble of the one-shot
// version and amortizes the schedule decode 8x.
#define B_    32
#define NST   8
#define NSUB  256
#define WIN   2048

#define STAGE_FLOATS (NST * 32 * 32)          // 8192 floats = 32 KB per stage
#define STAGE_BYTES  (STAGE_FLOATS * 4)
#define SMEM_TILE_OFF  (2 * STAGE_BYTES)              // 65536
#define SMEM_TW_OFF    (SMEM_TILE_OFF + 32 * 33 * 4)  // +4224
#define SMEM_MBAR_OFF  (SMEM_TW_OFF + 128)
#define SMEM_BYTES     (SMEM_MBAR_OFF + 16)

__device__ __forceinline__ uint32_t smem_u32(const void* p) {
    uint32_t a;
    asm("{ .reg .u64 t; cvta.to.shared.u64 t, %1; cvt.u32.u64 %0, t; }"
        : "=r"(a) : "l"(p));
    return a;
}

__device__ __forceinline__ void mbar_wait(uint32_t mb, uint32_t parity) {
    uint32_t done;
    asm volatile("{\n\t.reg .pred p;\n\t"
                 "mbarrier.try_wait.parity.acquire.cta.shared::cta.b64 p, [%1], %2;\n\t"
                 "selp.b32 %0, 1, 0, p;\n\t}"
                 : "=r"(done) : "r"(mb), "r"(parity) : "memory");
    if (!done) {
        asm volatile("{\n\t.reg .pred P1;\n\t"
                     "WL_%=:\n\t"
                     "mbarrier.try_wait.parity.acquire.cta.shared::cta.b64 P1, [%0], %1, 0x989680;\n\t"
                     "@P1 bra.uni WD_%=;\n\t"
                     "bra.uni WL_%=;\n\t"
                     "WD_%=:\n\t}"
                     :: "r"(mb), "r"(parity) : "memory");
    }
}

// ---------------- pipelined TMA kernel ----------------
__global__ __launch_bounds__(256)
void station_select_tma_pipe_kernel(const __grid_constant__ CUtensorMap tmap,
                                    const float* __restrict__ sched,
                                    float* __restrict__ out) {
    extern __shared__ __align__(128) char smem_raw[];
    float* stage = reinterpret_cast<float*>(smem_raw);            // [2][8][32][32]
    float (*tile)[33] = reinterpret_cast<float(*)[33]>(smem_raw + SMEM_TILE_OFF);
    int*       tw   = reinterpret_cast<int*>(smem_raw + SMEM_TW_OFF);
    uint64_t*  mbar = reinterpret_cast<uint64_t*>(smem_raw + SMEM_MBAR_OFF);

    const int b   = blockIdx.y;          // 32
    const int w0  = blockIdx.x * 32;     // 64 w tiles (fastest -> contiguous lines)
    const int tid = threadIdx.x;
    const int tx  = tid & 31;
    const int ty  = tid >> 5;

    const uint32_t mb0 = smem_u32(&mbar[0]);
    const uint32_t mb1 = smem_u32(&mbar[1]);

    if (tid == 0) {
        asm volatile("mbarrier.init.shared.b64 [%0], %1;" :: "r"(mb0), "r"(1) : "memory");
        asm volatile("mbarrier.init.shared.b64 [%0], %1;" :: "r"(mb1), "r"(1) : "memory");
    }
    // station decode once per CTA (exact: one-hot values are 0.0/1.0)
    if (tid < 32) {
        const float4* sp = reinterpret_cast<const float4*>(
            sched + ((size_t)b * WIN + (size_t)(w0 + tid)) * NST);
        const float4 a = sp[0];
        const float4 c = sp[1];
        const float tf = a.y + 2.f * a.z + 3.f * a.w +
                         4.f * c.x + 5.f * c.y + 6.f * c.z + 7.f * c.w;
        tw[tid] = (int)(tf + 0.5f);
    }
    __syncthreads();   // mbar init + tw visible

    // prologue: prefetch s-tile 0 into buffer 0
    if (tid == 0) {
        asm volatile("mbarrier.arrive.expect_tx.shared.b64 _, [%0], %1;"
                     :: "r"(mb0), "r"((uint32_t)STAGE_BYTES) : "memory");
        asm volatile("cp.async.bulk.tensor.3d.shared::cta.global.tile.mbarrier::complete_tx::bytes "
                     "[%0], [%1, {%2, %3, %4}], [%5];"
                     :: "r"(smem_u32(stage)), "l"(&tmap),
                        "r"(w0), "r"(0), "r"(b * NST), "r"(mb0) : "memory");
    }

    uint32_t ph0 = 0, ph1 = 0;   // per-buffer phase parity (uniform)
    const int t = tw[tx];        // station for this lane's w (uniform per lane across iters)

#pragma unroll 1
    for (int sT = 0; sT < NSUB / 32; sT++) {
        const int buf = sT & 1;
        const uint32_t mb_cur = buf ? mb1 : mb0;

        // prefetch next s-tile into the other buffer (its consumers finished
        // in iteration sT-1, before that iteration's mid-sync)
        if (tid == 0 && sT + 1 < NSUB / 32) {
            const uint32_t mb_nxt = buf ? mb0 : mb1;
            asm volatile("mbarrier.arrive.expect_tx.shared.b64 _, [%0], %1;"
                         :: "r"(mb_nxt), "r"((uint32_t)STAGE_BYTES) : "memory");
            asm volatile("cp.async.bulk.tensor.3d.shared::cta.global.tile.mbarrier::complete_tx::bytes "
                         "[%0], [%1, {%2, %3, %4}], [%5];"
                         :: "r"(smem_u32(stage + (buf ^ 1) * STAGE_FLOATS)), "l"(&tmap),
                            "r"(w0), "r"((sT + 1) * 32), "r"(b * NST), "r"(mb_nxt)
                         : "memory");
        }

        // wait for the current tile
        mbar_wait(mb_cur, buf ? ph1 : ph0);
        if (buf) ph1 ^= 1; else ph0 ^= 1;

        // smem select: addr % 128 == 4*tx -> conflict-free for any plane t
        const float* st = stage + buf * STAGE_FLOATS + t * (32 * 32);
        float v[4];
#pragma unroll
        for (int r = 0; r < 4; r++)
            v[r] = st[(ty + r * 8) * 32 + tx];

        __syncthreads();   // (A) prior iteration's tile reads complete

        // transpose tile: bank = (sl + tx) & 31 -> conflict-free
#pragma unroll
        for (int r = 0; r < 4; r++)
            tile[ty + r * 8][tx] = v[r];
        __syncthreads();   // (B)

        // coalesced stores along s: bank = (tx + wl) & 31 -> conflict-free
        const size_t s0 = (size_t)sT * 32;
#pragma unroll
        for (int r = 0; r < 4; r++) {
            const int wl = ty + r * 8;
            out[((size_t)b * WIN + (size_t)(w0 + wl)) * NSUB + s0 + (size_t)tx]
                = tile[tx][wl];
        }
    }
}

// ---------------- fallback: R1 LDG kernel ----------------
__global__ __launch_bounds__(256)
void station_select_ldg_kernel(const float* __restrict__ sched,
                               const float* __restrict__ csi,
                               float* __restrict__ out) {
    __shared__ float tile[32][33];
    __shared__ int   tw[32];

    const int b   = blockIdx.z;
    const int w0  = blockIdx.x * 32;
    const int s0  = blockIdx.y * 32;
    const int tid = threadIdx.x;
    const int tx  = tid & 31;
    const int ty  = tid >> 5;

    if (tid < 32) {
        const float4* sp = reinterpret_cast<const float4*>(
            sched + ((size_t)b * WIN + (size_t)(w0 + tid)) * NST);
        const float4 a = sp[0];
        const float4 c = sp[1];
        const float tf = a.y + 2.f * a.z + 3.f * a.w +
                         4.f * c.x + 5.f * c.y + 6.f * c.z + 7.f * c.w;
        tw[tid] = (int)(tf + 0.5f);
    }
    __syncthreads();

    const int t = tw[tx];
    const float* p = csi + ((size_t)(b * NST + t) * NSUB + (size_t)s0) * WIN
                         + (size_t)(w0 + tx);
    float v[4];
#pragma unroll
    for (int r = 0; r < 4; r++)
        v[r] = p[(size_t)(ty + r * 8) * WIN];
#pragma unroll
    for (int r = 0; r < 4; r++)
        tile[ty + r * 8][tx] = v[r];
    __syncthreads();

#pragma unroll
    for (int r = 0; r < 4; r++) {
        const int wl = ty + r * 8;
        out[((size_t)b * WIN + (size_t)(w0 + wl)) * NSUB + (size_t)(s0 + tx)]
            = tile[tx][wl];
    }
}

// ---------------- host ----------------
typedef CUresult (*tmap_encode_fn)(
    CUtensorMap*, CUtensorMapDataType, cuuint32_t, void*,
    const cuuint64_t*, const cuuint64_t*, const cuuint32_t*, const cuuint32_t*,
    CUtensorMapInterleave, CUtensorMapSwizzle, CUtensorMapL2promotion,
    CUtensorMapFloatOOBfill);

extern "C" void kernel_launch(void* const* d_in, const int* in_sizes, int n_in,
                              void* d_out, int out_size) {
    const float* sched = (const float*)d_in[0];
    const float* csi   = (const float*)d_in[1];
    if (n_in >= 2 && in_sizes[0] != 524288) {   // schedule = 32*2048*8 elems
        sched = (const float*)d_in[1];
        csi   = (const float*)d_in[0];
    }
    float* out = (float*)d_out;

    // tensormap: csi viewed as [w=2048][s=256][plane=256(=b*8+t)]
    void* fn = nullptr;
    cudaDriverEntryPointQueryResult qr = cudaDriverEntryPointSymbolNotFound;
#if CUDART_VERSION >= 12050
    cudaGetDriverEntryPointByVersion("cuTensorMapEncodeTiled", &fn, 12000,
                                     cudaEnableDefault, &qr);
#else
    cudaGetDriverEntryPoint("cuTensorMapEncodeTiled", &fn,
                            cudaEnableDefault, &qr);
#endif
    bool ok = false;
    CUtensorMap tmap;
    if (fn != nullptr && qr == cudaDriverEntryPointSuccess) {
        cuuint64_t dims[3]    = {WIN, NSUB, (cuuint64_t)B_ * NST};
        cuuint64_t strides[2] = {(cuuint64_t)WIN * 4,
                                 (cuuint64_t)WIN * NSUB * 4};
        cuuint32_t box[3]     = {32, 32, NST};
        cuuint32_t es[3]      = {1, 1, 1};
        ok = ((tmap_encode_fn)fn)(&tmap, CU_TENSOR_MAP_DATA_TYPE_FLOAT32, 3,
                                  (void*)csi, dims, strides, box, es,
                                  CU_TENSOR_MAP_INTERLEAVE_NONE,
                                  CU_TENSOR_MAP_SWIZZLE_NONE,
                                  CU_TENSOR_MAP_L2_PROMOTION_L2_128B,
                                  CU_TENSOR_MAP_FLOAT_OOB_FILL_NONE)
             == CUDA_SUCCESS;
    }

    if (ok) {
        cudaFuncSetAttribute(station_select_tma_pipe_kernel,
                             cudaFuncAttributeMaxDynamicSharedMemorySize,
                             SMEM_BYTES);
        dim3 grid(WIN / 32, B_, 1);
        station_select_tma_pipe_kernel<<<grid, 256, SMEM_BYTES>>>(tmap, sched, out);
    } else {
        dim3 grid(WIN / 32, NSUB / 32, B_);
        station_select_ldg_kernel<<<grid, 256>>>(sched, csi, out);
    }
}

// round 12
// speedup vs baseline: 1.0508x; 1.0508x over previous
#include <cuda_runtime.h>
#include <cuda.h>
#include <stdint.h>

// StationSelectionAggregator:
//   schedule: [B, WIN, N_ST]  one-hot float32
//   csi:      [B, N_ST, N_SUB, WIN] float32
//   out:      [B, WIN, N_SUB] float32
//   out[b,w,s] = csi[b, t(b,w), s, w]  (exact selection; schedule one-hot).
//
// R12: R10's one-shot TMA dense stage (best so far, 6.89 TB/s) with the box
// halved along s: 16 KB stage -> ~18.6 KB smem/CTA -> 8 CTAs/SM (occupancy
// ~100% vs 70.9%). DRAM request stream identical to R10 (same 128B inner
// rows); only resident-context count changes. Pipeline variants (R11) and
// all LDG variants (R1-R9) regressed; this isolates occupancy.
#define B_    32
#define NST   8
#define NSUB  256
#define WIN   2048

__device__ __forceinline__ uint32_t smem_u32(const void* p) {
    uint32_t a;
    asm("{ .reg .u64 t; cvta.to.shared.u64 t, %1; cvt.u32.u64 %0, t; }"
        : "=r"(a) : "l"(p));
    return a;
}

__device__ __forceinline__ void mbar_wait0(uint32_t mb) {
    uint32_t done;
    asm volatile("{\n\t.reg .pred p;\n\t"
                 "mbarrier.try_wait.parity.acquire.cta.shared::cta.b64 p, [%1], %2;\n\t"
                 "selp.b32 %0, 1, 0, p;\n\t}"
                 : "=r"(done) : "r"(mb), "r"(0u) : "memory");
    if (!done) {
        asm volatile("{\n\t.reg .pred P1;\n\t"
                     "WL_%=:\n\t"
                     "mbarrier.try_wait.parity.acquire.cta.shared::cta.b64 P1, [%0], %1, 0x989680;\n\t"
                     "@P1 bra.uni WD_%=;\n\t"
                     "bra.uni WL_%=;\n\t"
                     "WD_%=:\n\t}"
                     :: "r"(mb), "r"(0u) : "memory");
    }
}

// ---------------- one-shot TMA kernel, 16 KB box ----------------
__global__ __launch_bounds__(256)
void station_select_tma_kernel(const __grid_constant__ CUtensorMap tmap,
                               const float* __restrict__ sched,
                               float* __restrict__ out) {
    // blockIdx.x : w tile (64, fastest), .y : s tile (16), .z : batch (32)
    __shared__ __align__(128) float stage[NST][16][32];  // 16 KB TMA dest
    __shared__ float tile[16][34];                       // stride 34: conflict-free both phases
    __shared__ int   tw[32];
    __shared__ __align__(8) uint64_t mbar;

    const int b   = blockIdx.z;
    const int w0  = blockIdx.x * 32;
    const int s0  = blockIdx.y * 16;
    const int tid = threadIdx.x;
    const int tx  = tid & 31;
    const int ty  = tid >> 5;        // 0..7

    const uint32_t mb = smem_u32(&mbar);

    if (tid == 0) {
        asm volatile("mbarrier.init.shared.b64 [%0], %1;"
                     :: "r"(mb), "r"(1) : "memory");
        asm volatile("mbarrier.arrive.expect_tx.shared.b64 _, [%0], %1;"
                     :: "r"(mb), "r"((uint32_t)(NST * 16 * 32 * 4)) : "memory");
        asm volatile("cp.async.bulk.tensor.3d.shared::cta.global.tile.mbarrier::complete_tx::bytes "
                     "[%0], [%1, {%2, %3, %4}], [%5];"
                     :: "r"(smem_u32(stage)), "l"(&tmap),
                        "r"(w0), "r"(s0), "r"(b * NST), "r"(mb)
                     : "memory");
    }
    // station decode overlaps the TMA fill (exact: one-hot values are 0.0/1.0)
    if (tid < 32) {
        const float4* sp = reinterpret_cast<const float4*>(
            sched + ((size_t)b * WIN + (size_t)(w0 + tid)) * NST);
        const float4 a = sp[0];
        const float4 c = sp[1];
        const float tf = a.y + 2.f * a.z + 3.f * a.w +
                         4.f * c.x + 5.f * c.y + 6.f * c.z + 7.f * c.w;
        tw[tid] = (int)(tf + 0.5f);
    }
    __syncthreads();   // publishes mbar init + tw

    mbar_wait0(mb);

    // smem select: addr%128 == 4*tx -> conflict-free for any plane t
    const int t = tw[tx];
    const float v0 = stage[t][ty][tx];
    const float v1 = stage[t][ty + 8][tx];

    // transpose tile (stride 34): write banks (2*ty + tx)&31 all distinct
    tile[ty][tx]     = v0;
    tile[ty + 8][tx] = v1;
    __syncthreads();

    // stores: warp ty covers w rows 4*ty..4*ty+3; lanes split into two
    // 16-wide halves over s. read banks (2*sl + wl): even/odd disjoint.
    const int h  = tx >> 4;          // 0/1 -> which w row in the pair
    const int sl = tx & 15;          // s within tile
#pragma unroll
    for (int rr = 0; rr < 2; rr++) {
        const int wl = 4 * ty + 2 * rr + h;
        out[((size_t)b * WIN + (size_t)(w0 + wl)) * NSUB + (size_t)(s0 + sl)]
            = tile[sl][wl];
    }
}

// ---------------- fallback: R1 LDG kernel ----------------
__global__ __launch_bounds__(256)
void station_select_ldg_kernel(const float* __restrict__ sched,
                               const float* __restrict__ csi,
                               float* __restrict__ out) {
    __shared__ float tile[32][33];
    __shared__ int   tw[32];

    const int b   = blockIdx.z;
    const int w0  = blockIdx.x * 32;
    const int s0  = blockIdx.y * 32;
    const int tid = threadIdx.x;
    const int tx  = tid & 31;
    const int ty  = tid >> 5;

    if (tid < 32) {
        const float4* sp = reinterpret_cast<const float4*>(
            sched + ((size_t)b * WIN + (size_t)(w0 + tid)) * NST);
        const float4 a = sp[0];
        const float4 c = sp[1];
        const float tf = a.y + 2.f * a.z + 3.f * a.w +
                         4.f * c.x + 5.f * c.y + 6.f * c.z + 7.f * c.w;
        tw[tid] = (int)(tf + 0.5f);
    }
    __syncthreads();

    const int t = tw[tx];
    const float* p = csi + ((size_t)(b * NST + t) * NSUB + (size_t)s0) * WIN
                         + (size_t)(w0 + tx);
    float v[4];
#pragma unroll
    for (int r = 0; r < 4; r++)
        v[r] = p[(size_t)(ty + r * 8) * WIN];
#pragma unroll
    for (int r = 0; r < 4; r++)
        tile[ty + r * 8][tx] = v[r];
    __syncthreads();

#pragma unroll
    for (int r = 0; r < 4; r++) {
        const int wl = ty + r * 8;
        out[((size_t)b * WIN + (size_t)(w0 + wl)) * NSUB + (size_t)(s0 + tx)]
            = tile[tx][wl];
    }
}

// ---------------- host ----------------
typedef CUresult (*tmap_encode_fn)(
    CUtensorMap*, CUtensorMapDataType, cuuint32_t, void*,
    const cuuint64_t*, const cuuint64_t*, const cuuint32_t*, const cuuint32_t*,
    CUtensorMapInterleave, CUtensorMapSwizzle, CUtensorMapL2promotion,
    CUtensorMapFloatOOBfill);

extern "C" void kernel_launch(void* const* d_in, const int* in_sizes, int n_in,
                              void* d_out, int out_size) {
    const float* sched = (const float*)d_in[0];
    const float* csi   = (const float*)d_in[1];
    if (n_in >= 2 && in_sizes[0] != 524288) {   // schedule = 32*2048*8 elems
        sched = (const float*)d_in[1];
        csi   = (const float*)d_in[0];
    }
    float* out = (float*)d_out;

    // tensormap: csi viewed as [w=2048][s=256][plane=256(=b*8+t)]
    void* fn = nullptr;
    cudaDriverEntryPointQueryResult qr = cudaDriverEntryPointSymbolNotFound;
#if CUDART_VERSION >= 12050
    cudaGetDriverEntryPointByVersion("cuTensorMapEncodeTiled", &fn, 12000,
                                     cudaEnableDefault, &qr);
#else
    cudaGetDriverEntryPoint("cuTensorMapEncodeTiled", &fn,
                            cudaEnableDefault, &qr);
#endif
    bool ok = false;
    CUtensorMap tmap;
    if (fn != nullptr && qr == cudaDriverEntryPointSuccess) {
        cuuint64_t dims[3]    = {WIN, NSUB, (cuuint64_t)B_ * NST};
        cuuint64_t strides[2] = {(cuuint64_t)WIN * 4,
                                 (cuuint64_t)WIN * NSUB * 4};
        cuuint32_t box[3]     = {32, 16, NST};
        cuuint32_t es[3]      = {1, 1, 1};
        ok = ((tmap_encode_fn)fn)(&tmap, CU_TENSOR_MAP_DATA_TYPE_FLOAT32, 3,
                                  (void*)csi, dims, strides, box, es,
                                  CU_TENSOR_MAP_INTERLEAVE_NONE,
                                  CU_TENSOR_MAP_SWIZZLE_NONE,
                                  CU_TENSOR_MAP_L2_PROMOTION_L2_128B,
                                  CU_TENSOR_MAP_FLOAT_OOB_FILL_NONE)
             == CUDA_SUCCESS;
    }

    if (ok) {
        dim3 grid(WIN / 32, NSUB / 16, B_);
        station_select_tma_kernel<<<grid, 256>>>(tmap, sched, out);
    } else {
        dim3 grid(WIN / 32, NSUB / 32, B_);
        station_select_ldg_kernel<<<grid, 256>>>(sched, csi, out);
    }
}